// round 15
// baseline (speedup 1.0000x reference)
#include <cuda_runtime.h>
#include <cuda_fp16.h>
#include <stdint.h>

// Problem dims
#define B_  2
#define S_  2048
#define D_  1024
#define H_  16
#define HD_ 64
#define BS_ (B_ * S_)         // 4096
#define NX  (BS_ * D_)
#define NW  (H_ * D_ * HD_)
#define LOG2E 1.4426950408889634f

// fp16 scratch (device globals — allocation-guard safe)
__device__ __align__(16) __half g_xh[NX];
__device__ __align__(16) __half g_wqh[NW], g_wkh[NW], g_wvh[NW], g_woh[D_ * D_];
__device__ float g_bqs[H_ * HD_];                    // bq * 0.125 * log2e
__device__ __align__(16) __half g_q[B_ * H_ * S_ * HD_];   // pre-scaled (exp2 domain)
__device__ __align__(16) __half g_k[B_ * H_ * S_ * HD_];
__device__ __align__(16) __half g_v[B_ * H_ * S_ * HD_];
__device__ __align__(16) __half g_wv[BS_ * D_];            // [B,S,H*HD]

__device__ __forceinline__ uint32_t smem_u32(const void* p) {
    uint32_t a;
    asm("{ .reg .u64 t; cvta.to.shared.u64 t, %1; cvt.u32.u64 %0, t; }"
        : "=r"(a) : "l"(p));
    return a;
}

__device__ __forceinline__ void mma_f16(float c[4], const uint32_t a[4],
                                        uint32_t b0, uint32_t b1) {
    asm volatile(
        "mma.sync.aligned.m16n8k16.row.col.f32.f16.f16.f32 "
        "{%0,%1,%2,%3}, {%4,%5,%6,%7}, {%8,%9}, {%0,%1,%2,%3};"
        : "+f"(c[0]), "+f"(c[1]), "+f"(c[2]), "+f"(c[3])
        : "r"(a[0]), "r"(a[1]), "r"(a[2]), "r"(a[3]), "r"(b0), "r"(b1));
}
__device__ __forceinline__ void ldm4(uint32_t r[4], uint32_t addr) {
    asm volatile("ldmatrix.sync.aligned.m8n8.x4.shared.b16 {%0,%1,%2,%3}, [%4];"
        : "=r"(r[0]), "=r"(r[1]), "=r"(r[2]), "=r"(r[3]) : "r"(addr));
}
__device__ __forceinline__ void ldm4t(uint32_t r[4], uint32_t addr) {
    asm volatile("ldmatrix.sync.aligned.m8n8.x4.trans.shared.b16 {%0,%1,%2,%3}, [%4];"
        : "=r"(r[0]), "=r"(r[1]), "=r"(r[2]), "=r"(r[3]) : "r"(addr));
}

#define CP16(d, s)  asm volatile("cp.async.cg.shared.global [%0], [%1], 16;" :: "r"(d), "l"(s))
#define CPCOMMIT()  asm volatile("cp.async.commit_group;")
#define CPWAIT(n)   asm volatile("cp.async.wait_group %0;" :: "n"(n))

#define PK2(x, y) ({ __half2 _h = __floats2half2_rn((x), (y)); *(uint32_t*)&_h; })

// ---------------------------------------------------------------------------
// Convert (vectorized float4): x, Wq(*0.125*log2e), Wk, Wv, Wo -> fp16; bq
// ---------------------------------------------------------------------------
#define NX4 (NX / 4)
#define NW4 (NW / 4)
#define ND4 (D_ * D_ / 4)
__device__ __forceinline__ void cvt4(__half* dst, const float* src, long long i, float s) {
    float4 v = ((const float4*)src)[i];
    __half2 h0 = __floats2half2_rn(v.x * s, v.y * s);
    __half2 h1 = __floats2half2_rn(v.z * s, v.w * s);
    ((uint2*)dst)[i] = make_uint2(*(uint32_t*)&h0, *(uint32_t*)&h1);
}
__global__ __launch_bounds__(256) void convert_kernel(
    const float* __restrict__ x,  const float* __restrict__ Wq,
    const float* __restrict__ bq, const float* __restrict__ Wk,
    const float* __restrict__ Wv, const float* __restrict__ Wo)
{
    long long i = (long long)blockIdx.x * 256 + threadIdx.x;
    if (i < NX4) { cvt4(g_xh, x, i, 1.f); return; }
    i -= NX4;
    if (i < NW4) { cvt4(g_wqh, Wq, i, 0.125f * LOG2E); return; }
    i -= NW4;
    if (i < NW4) { cvt4(g_wkh, Wk, i, 1.f); return; }
    i -= NW4;
    if (i < NW4) { cvt4(g_wvh, Wv, i, 1.f); return; }
    i -= NW4;
    if (i < ND4) { cvt4(g_woh, Wo, i, 1.f); return; }
    i -= ND4;
    if (i < H_ * HD_) g_bqs[i] = bq[i] * 0.125f * LOG2E;
}

// ---------------------------------------------------------------------------
// QKV projection (fp16, R12-proven): 512 threads, 128x256x32, warp tile 32x64.
// 3-buffer ring. sA [row][k] stride 40; sB [k][n] stride 264 (trans ldmatrix).
// grid (32, 4, 3).
// ---------------------------------------------------------------------------
#define QA_ST 40
#define QAW   (128 * QA_ST)
#define QB_ST 264
#define QBW   (32 * QB_ST)
#define QSTG  (QAW + QBW)
#define QKV_SMEM (3 * QSTG * 2)   // 81408 bytes

__global__ __launch_bounds__(512, 1) void qkv_kernel(
    const float* __restrict__ bk, const float* __restrict__ bv)
{
    extern __shared__ __half hsm[];
    const int rt = blockIdx.x, hp = blockIdx.y, m = blockIdx.z;
    const __half* W    = (m == 0) ? g_wqh : (m == 1) ? g_wkh : g_wvh;
    const float*  bias = (m == 0) ? g_bqs : (m == 1) ? bk : bv;
    __half*       out  = (m == 0) ? g_q : (m == 1) ? g_k : g_v;

    const int tid  = threadIdx.x;
    const int wid  = tid >> 5;
    const int lane = tid & 31;
    const int wm   = wid >> 2, wn = wid & 3;
    const int ql   = lane & 3, qr = lane >> 2;
    const int row0 = rt * 128;
    const int h0   = hp * 4;

    const uint32_t sm0 = smem_u32(hsm);
    const uint32_t aLane = ((wm * 32 + (lane & 15)) * QA_ST) * 2 + (lane >> 4) * 16;
    const int klane = (lane & 7) + ((lane >> 3) & 1) * 8;
    const uint32_t bLane = (klane * QB_ST + (lane >> 4) * 8 + wn * 64) * 2;

    float acc[2][8][4];
    #pragma unroll
    for (int mi = 0; mi < 2; mi++)
        #pragma unroll
        for (int ni = 0; ni < 8; ni++)
            #pragma unroll
            for (int c = 0; c < 4; c++) acc[mi][ni][c] = 0.f;

    #define QKV_STAGE(c, s) {                                                  \
        uint32_t sb = sm0 + (s) * QSTG * 2;                                    \
        {   int g = tid; int row = g >> 2; int kg = (g & 3) * 8;               \
            CP16(sb + (row * QA_ST + kg) * 2,                                  \
                 &g_xh[(size_t)(row0 + row) * D_ + (c) * 32 + kg]);            \
        }                                                                      \
        _Pragma("unroll")                                                      \
        for (int i = 0; i < 2; i++) {                                          \
            int g = i * 512 + tid; int k = g >> 5; int n8 = (g & 31) * 8;      \
            CP16(sb + (QAW + k * QB_ST + n8) * 2,                              \
                 &W[((size_t)(h0 + (n8 >> 6)) * D_ + (c) * 32 + k) * HD_ + (n8 & 63)]); \
        }                                                                      \
    }

    QKV_STAGE(0, 0); CPCOMMIT();
    QKV_STAGE(1, 1); CPCOMMIT();

    for (int c = 0; c < 32; c++) {
        const int cur = c % 3;
        CPWAIT(1);
        __syncthreads();
        if (c + 2 < 32) { QKV_STAGE(c + 2, (c + 2) % 3); }
        CPCOMMIT();

        const uint32_t sAb = sm0 + cur * QSTG * 2;
        const uint32_t sBb = sAb + QAW * 2;

        #pragma unroll
        for (int kk = 0; kk < 2; kk++) {
            uint32_t a[2][4];
            #pragma unroll
            for (int mi = 0; mi < 2; mi++)
                ldm4(a[mi], sAb + aLane + mi * 16 * QA_ST * 2 + kk * 32);
            uint32_t bb[4][4];
            #pragma unroll
            for (int nj = 0; nj < 4; nj++)
                ldm4t(bb[nj], sBb + bLane + (kk * 16 * QB_ST + nj * 16) * 2);
            #pragma unroll
            for (int mi = 0; mi < 2; mi++)
                #pragma unroll
                for (int nj = 0; nj < 4; nj++) {
                    mma_f16(acc[mi][2 * nj],     a[mi], bb[nj][0], bb[nj][1]);
                    mma_f16(acc[mi][2 * nj + 1], a[mi], bb[nj][2], bb[nj][3]);
                }
        }
    }

    #pragma unroll
    for (int mi = 0; mi < 2; mi++) {
        int row = row0 + wm * 32 + mi * 16 + qr;
        int bb2 = row >> 11;
        int s   = row & (S_ - 1);
        #pragma unroll
        for (int ni = 0; ni < 8; ni++) {
            int cl = wn * 64 + ni * 8 + 2 * ql;
            int h  = h0 + (cl >> 6);
            int e  = cl & 63;
            float bv0 = bias[h * HD_ + e];
            float bv1 = bias[h * HD_ + e + 1];
            __half* p0 = out + (((size_t)bb2 * H_ + h) * S_ + s) * HD_ + e;
            __half* p1 = out + (((size_t)bb2 * H_ + h) * S_ + s + 8) * HD_ + e;
            *(__half2*)p0 = __floats2half2_rn(acc[mi][ni][0] + bv0, acc[mi][ni][1] + bv1);
            *(__half2*)p1 = __floats2half2_rn(acc[mi][ni][2] + bv0, acc[mi][ni][3] + bv1);
        }
    }
}

// ---------------------------------------------------------------------------
// Flash attention (causal, fp16, exp2-domain, NO running max, P in registers).
// 128 queries/block, 8 warps x 16 rows, double-buffered K/V.
// grid (16 reversed, 32), 256 threads, occupancy 2.
// ---------------------------------------------------------------------------
#define AT_ST 72
#define AK_W (64 * AT_ST)
#define AV_W (64 * AT_ST)
#define AQ_OFF (2 * AK_W + 2 * AV_W)
#define AQ_W  (128 * AT_ST)
#define ATT_SMEM ((AQ_OFF + AQ_W) * 2)

__global__ __launch_bounds__(256, 2) void attn_kernel()
{
    extern __shared__ __half hsm[];

    const int qt = 15 - blockIdx.x;
    const int bh = blockIdx.y;
    const int b  = bh >> 4;
    const int h  = bh & 15;
    const int tid  = threadIdx.x;
    const int w    = tid >> 5;
    const int lane = tid & 31;
    const int qr   = lane >> 2;
    const int ql   = lane & 3;

    const __half* Qb = g_q + (size_t)bh * S_ * HD_;
    const __half* Kb = g_k + (size_t)bh * S_ * HD_;
    const __half* Vb = g_v + (size_t)bh * S_ * HD_;

    const uint32_t sk_b = smem_u32(hsm);
    const uint32_t sv_b = sk_b + 2 * AK_W * 2;
    const uint32_t sq_b = sk_b + AQ_OFF * 2;
    const uint32_t aoff = ((w * 16 + (lane & 15)) * AT_ST) * 2 + (lane >> 4) * 16;
    const uint32_t koff = ((lane & 15) * AT_ST) * 2 + (lane >> 4) * 16;
    const int klane = (lane & 7) + ((lane >> 3) & 1) * 8;
    const uint32_t voff = (klane * AT_ST + (lane >> 4) * 8) * 2;

    // ---- stage Q (exp2-domain pre-scaled), extract A fragments ----
    #pragma unroll
    for (int i = 0; i < 4; i++) {
        int g = i * 256 + tid;
        int row = g >> 3, kg = (g & 7) * 8;
        CP16(sq_b + (row * AT_ST + kg) * 2, &Qb[(size_t)(qt * 128 + row) * HD_ + kg]);
    }
    CPCOMMIT(); CPWAIT(0);
    __syncthreads();

    uint32_t qa[4][4];
    #pragma unroll
    for (int kk = 0; kk < 4; kk++) ldm4(qa[kk], sq_b + aoff + kk * 32);

    #define ATT_STAGE(kt, s) {                                                 \
        _Pragma("unroll")                                                      \
        for (int i = 0; i < 4; i++) {                                          \
            int g = i * 256 + tid;                                             \
            int sel = g >> 9; int row = (g >> 3) & 63; int kg = (g & 7) * 8;   \
            uint32_t base = sel ? (sv_b + (s) * AV_W * 2) : (sk_b + (s) * AK_W * 2); \
            const __half* src = sel ? &Vb[(size_t)((kt) * 64 + row) * HD_ + kg] \
                                    : &Kb[(size_t)((kt) * 64 + row) * HD_ + kg]; \
            CP16(base + (row * AT_ST + kg) * 2, src);                          \
        }                                                                      \
    }

    ATT_STAGE(0, 0); CPCOMMIT();

    float O[8][4];
    #pragma unroll
    for (int n = 0; n < 8; n++)
        #pragma unroll
        for (int c = 0; c < 4; c++) O[n][c] = 0.f;
    float l0 = 0.f, l1 = 0.f;          // deferred row-sum (no max needed)

    const int rbase = qt * 128 + w * 16;
    const int nkt = 2 * qt + 2;

    for (int kt = 0; kt < nkt; kt++) {
        const int buf = kt & 1;
        CPWAIT(0);
        __syncthreads();
        if (kt + 1 < nkt) { ATT_STAGE(kt + 1, buf ^ 1); }
        CPCOMMIT();

        if (kt * 64 > rbase + 15) continue;   // fully masked for this warp

        // ---- QK^T (exp2-domain logits) ----
        const uint32_t kbase = sk_b + buf * AK_W * 2;
        float sc[8][4];
        #pragma unroll
        for (int n = 0; n < 8; n++)
            #pragma unroll
            for (int c = 0; c < 4; c++) sc[n][c] = 0.f;
        #pragma unroll
        for (int kk = 0; kk < 4; kk++) {
            #pragma unroll
            for (int j = 0; j < 4; j++) {
                uint32_t kb[4];
                ldm4(kb, kbase + koff + j * 16 * AT_ST * 2 + kk * 32);
                mma_f16(sc[2 * j],     qa[kk], kb[0], kb[2]);
                mma_f16(sc[2 * j + 1], qa[kk], kb[1], kb[3]);
            }
        }

        if (kt * 64 + 63 > rbase) {    // partial causal mask
            const int r0 = rbase + qr;
            const int c0 = kt * 64;
            #pragma unroll
            for (int n = 0; n < 8; n++) {
                int cg = c0 + n * 8 + 2 * ql;
                if (cg     > r0)     sc[n][0] = -1e30f;
                if (cg + 1 > r0)     sc[n][1] = -1e30f;
                if (cg     > r0 + 8) sc[n][2] = -1e30f;
                if (cg + 1 > r0 + 8) sc[n][3] = -1e30f;
            }
        }

        // ---- p = exp2(s); accumulate partial row sums ----
        #pragma unroll
        for (int n = 0; n < 8; n++) {
            sc[n][0] = exp2f(sc[n][0]);
            sc[n][1] = exp2f(sc[n][1]);
            sc[n][2] = exp2f(sc[n][2]);
            sc[n][3] = exp2f(sc[n][3]);
            l0 += sc[n][0] + sc[n][1];
            l1 += sc[n][2] + sc[n][3];
        }

        // ---- P @ V, P directly as A-fragments (no smem round trip) ----
        const uint32_t vbase = sv_b + buf * AV_W * 2;
        #pragma unroll
        for (int kk = 0; kk < 4; kk++) {
            uint32_t pa[4];
            pa[0] = PK2(sc[2 * kk][0],     sc[2 * kk][1]);
            pa[1] = PK2(sc[2 * kk][2],     sc[2 * kk][3]);
            pa[2] = PK2(sc[2 * kk + 1][0], sc[2 * kk + 1][1]);
            pa[3] = PK2(sc[2 * kk + 1][2], sc[2 * kk + 1][3]);
            #pragma unroll
            for (int j = 0; j < 4; j++) {
                uint32_t vb[4];
                ldm4t(vb, vbase + voff + (kk * 16 * AT_ST + j * 16) * 2);
                mma_f16(O[2 * j],     pa, vb[0], vb[1]);
                mma_f16(O[2 * j + 1], pa, vb[2], vb[3]);
            }
        }
    }

    // ---- reduce l across the quad, normalize, store ----
    l0 += __shfl_xor_sync(0xffffffffu, l0, 1);
    l0 += __shfl_xor_sync(0xffffffffu, l0, 2);
    l1 += __shfl_xor_sync(0xffffffffu, l1, 1);
    l1 += __shfl_xor_sync(0xffffffffu, l1, 2);
    float inv0 = 1.f / l0, inv1 = 1.f / l1;
    int r0g = qt * 128 + w * 16 + qr;
    __half* base0 = g_wv + ((size_t)b * S_ + r0g) * D_ + h * HD_;
    __half* base1 = g_wv + ((size_t)b * S_ + r0g + 8) * D_ + h * HD_;
    #pragma unroll
    for (int n = 0; n < 8; n++) {
        int cc = n * 8 + 2 * ql;
        *(__half2*)&base0[cc] = __floats2half2_rn(O[n][0] * inv0, O[n][1] * inv0);
        *(__half2*)&base1[cc] = __floats2half2_rn(O[n][2] * inv1, O[n][3] * inv1);
    }
}

// ---------------------------------------------------------------------------
// Output projection (fp16, R12-proven): 512 threads, 128x256x32, 3-buffer ring.
// A [row][k], B [n][k] stride 40, non-trans ldmatrix. grid (32, 4).
// ---------------------------------------------------------------------------
#define OA_ST 40
#define OAW   (128 * OA_ST)
#define OBW   (256 * OA_ST)
#define OSTG  (OAW + OBW)
#define OP_SMEM (3 * OSTG * 2)   // 92160 bytes

__global__ __launch_bounds__(512, 1) void oproj_kernel(
    const float* __restrict__ bo, float* __restrict__ out)
{
    extern __shared__ __half hsm[];
    const int rt = blockIdx.x, ct = blockIdx.y;

    const int tid  = threadIdx.x;
    const int wid  = tid >> 5;
    const int lane = tid & 31;
    const int wm   = wid >> 2, wn = wid & 3;
    const int ql   = lane & 3, qr = lane >> 2;
    const int row0 = rt * 128;
    const int col0 = ct * 256;

    const uint32_t sm0 = smem_u32(hsm);
    const uint32_t aLane = ((wm * 32 + (lane & 15)) * OA_ST) * 2 + (lane >> 4) * 16;
    const uint32_t bLane = ((wn * 64 + (lane & 15)) * OA_ST) * 2 + (lane >> 4) * 16;

    float acc[2][8][4];
    #pragma unroll
    for (int mi = 0; mi < 2; mi++)
        #pragma unroll
        for (int ni = 0; ni < 8; ni++)
            #pragma unroll
            for (int c = 0; c < 4; c++) acc[mi][ni][c] = 0.f;

    #define OP_STAGE(c, s) {                                                   \
        uint32_t sb = sm0 + (s) * OSTG * 2;                                    \
        {   int g = tid; int row = g >> 2; int kg = (g & 3) * 8;               \
            CP16(sb + (row * OA_ST + kg) * 2,                                  \
                 &g_wv[(size_t)(row0 + row) * D_ + (c) * 32 + kg]);            \
        }                                                                      \
        _Pragma("unroll")                                                      \
        for (int i = 0; i < 2; i++) {                                          \
            int g = i * 512 + tid; int n = g >> 2; int kg = (g & 3) * 8;       \
            CP16(sb + (OAW + n * OA_ST + kg) * 2,                              \
                 &g_woh[(size_t)(col0 + n) * D_ + (c) * 32 + kg]);             \
        }                                                                      \
    }

    OP_STAGE(0, 0); CPCOMMIT();
    OP_STAGE(1, 1); CPCOMMIT();

    for (int c = 0; c < 32; c++) {
        const int cur = c % 3;
        CPWAIT(1);
        __syncthreads();
        if (c + 2 < 32) { OP_STAGE(c + 2, (c + 2) % 3); }
        CPCOMMIT();

        const uint32_t sAb = sm0 + cur * OSTG * 2;
        const uint32_t sBb = sAb + OAW * 2;

        #pragma unroll
        for (int kk = 0; kk < 2; kk++) {
            uint32_t a[2][4];
            #pragma unroll
            for (int mi = 0; mi < 2; mi++)
                ldm4(a[mi], sAb + aLane + mi * 16 * OA_ST * 2 + kk * 32);
            uint32_t bb[4][4];
            #pragma unroll
            for (int nj = 0; nj < 4; nj++)
                ldm4(bb[nj], sBb + bLane + nj * 16 * OA_ST * 2 + kk * 32);
            #pragma unroll
            for (int mi = 0; mi < 2; mi++)
                #pragma unroll
                for (int nj = 0; nj < 4; nj++) {
                    mma_f16(acc[mi][2 * nj],     a[mi], bb[nj][0], bb[nj][2]);
                    mma_f16(acc[mi][2 * nj + 1], a[mi], bb[nj][1], bb[nj][3]);
                }
        }
    }

    #pragma unroll
    for (int mi = 0; mi < 2; mi++) {
        int row = row0 + wm * 32 + mi * 16 + qr;
        #pragma unroll
        for (int ni = 0; ni < 8; ni++) {
            int col = col0 + wn * 64 + ni * 8 + 2 * ql;
            float bv0 = bo[col], bv1 = bo[col + 1];
            *(float2*)&out[(size_t)row * D_ + col] =
                make_float2(acc[mi][ni][0] + bv0, acc[mi][ni][1] + bv1);
            *(float2*)&out[(size_t)(row + 8) * D_ + col] =
                make_float2(acc[mi][ni][2] + bv0, acc[mi][ni][3] + bv1);
        }
    }
}

// ---------------------------------------------------------------------------
// Launch. metadata order: x, Wq, bq, Wk, bk, Wv, bv, Wo, bo
// ---------------------------------------------------------------------------
extern "C" void kernel_launch(void* const* d_in, const int* in_sizes, int n_in,
                              void* d_out, int out_size)
{
    const float* x  = (const float*)d_in[0];
    const float* Wq = (const float*)d_in[1];
    const float* bq = (const float*)d_in[2];
    const float* Wk = (const float*)d_in[3];
    const float* bk = (const float*)d_in[4];
    const float* Wv = (const float*)d_in[5];
    const float* bv = (const float*)d_in[6];
    const float* Wo = (const float*)d_in[7];
    const float* bo = (const float*)d_in[8];
    float* out = (float*)d_out;

    cudaFuncSetAttribute(qkv_kernel,   cudaFuncAttributeMaxDynamicSharedMemorySize, QKV_SMEM);
    cudaFuncSetAttribute(attn_kernel,  cudaFuncAttributeMaxDynamicSharedMemorySize, ATT_SMEM);
    cudaFuncSetAttribute(oproj_kernel, cudaFuncAttributeMaxDynamicSharedMemorySize, OP_SMEM);

    const long long ntot = (long long)NX4 + 3LL * NW4 + ND4 + H_ * HD_;
    convert_kernel<<<(int)((ntot + 255) / 256), 256>>>(x, Wq, bq, Wk, Wv, Wo);

    qkv_kernel<<<dim3(BS_ / 128, H_ / 4, 3), 512, QKV_SMEM>>>(bk, bv);

    attn_kernel<<<dim3(16, 32), 256, ATT_SMEM>>>();

    oproj_kernel<<<dim3(BS_ / 128, D_ / 256), 512, OP_SMEM>>>(bo, out);
}

// round 16
// speedup vs baseline: 1.5272x; 1.5272x over previous
#include <cuda_runtime.h>
#include <cuda_fp16.h>
#include <stdint.h>

// Problem dims
#define B_  2
#define S_  2048
#define D_  1024
#define H_  16
#define HD_ 64
#define BS_ (B_ * S_)         // 4096
#define NX  (BS_ * D_)
#define NW  (H_ * D_ * HD_)
#define LOG2E 1.4426950408889634f

// fp16 scratch (device globals — allocation-guard safe)
__device__ __align__(16) __half g_xh[NX];
__device__ __align__(16) __half g_wqh[NW], g_wkh[NW], g_wvh[NW], g_woh[D_ * D_];
__device__ float g_bqs[H_ * HD_];                    // bq * 0.125 * log2e
__device__ __align__(16) __half g_q[B_ * H_ * S_ * HD_];   // pre-scaled (exp2 domain)
__device__ __align__(16) __half g_k[B_ * H_ * S_ * HD_];
__device__ __align__(16) __half g_v[B_ * H_ * S_ * HD_];
__device__ __align__(16) __half g_wv[BS_ * D_];            // [B,S,H*HD]

__device__ __forceinline__ uint32_t smem_u32(const void* p) {
    uint32_t a;
    asm("{ .reg .u64 t; cvta.to.shared.u64 t, %1; cvt.u32.u64 %0, t; }"
        : "=r"(a) : "l"(p));
    return a;
}

__device__ __forceinline__ void mma_f16(float c[4], const uint32_t a[4],
                                        uint32_t b0, uint32_t b1) {
    asm volatile(
        "mma.sync.aligned.m16n8k16.row.col.f32.f16.f16.f32 "
        "{%0,%1,%2,%3}, {%4,%5,%6,%7}, {%8,%9}, {%0,%1,%2,%3};"
        : "+f"(c[0]), "+f"(c[1]), "+f"(c[2]), "+f"(c[3])
        : "r"(a[0]), "r"(a[1]), "r"(a[2]), "r"(a[3]), "r"(b0), "r"(b1));
}
__device__ __forceinline__ void ldm4(uint32_t r[4], uint32_t addr) {
    asm volatile("ldmatrix.sync.aligned.m8n8.x4.shared.b16 {%0,%1,%2,%3}, [%4];"
        : "=r"(r[0]), "=r"(r[1]), "=r"(r[2]), "=r"(r[3]) : "r"(addr));
}
__device__ __forceinline__ void ldm4t(uint32_t r[4], uint32_t addr) {
    asm volatile("ldmatrix.sync.aligned.m8n8.x4.trans.shared.b16 {%0,%1,%2,%3}, [%4];"
        : "=r"(r[0]), "=r"(r[1]), "=r"(r[2]), "=r"(r[3]) : "r"(addr));
}

#define CP16(d, s)  asm volatile("cp.async.cg.shared.global [%0], [%1], 16;" :: "r"(d), "l"(s))
#define CPCOMMIT()  asm volatile("cp.async.commit_group;")
#define CPWAIT(n)   asm volatile("cp.async.wait_group %0;" :: "n"(n))

#define PK2(x, y) ({ __half2 _h = __floats2half2_rn((x), (y)); *(uint32_t*)&_h; })

// ---------------------------------------------------------------------------
// Convert (vectorized float4): x, Wq(*0.125*log2e), Wk, Wv, Wo -> fp16; bq
// ---------------------------------------------------------------------------
#define NX4 (NX / 4)
#define NW4 (NW / 4)
#define ND4 (D_ * D_ / 4)
__device__ __forceinline__ void cvt4(__half* dst, const float* src, long long i, float s) {
    float4 v = ((const float4*)src)[i];
    __half2 h0 = __floats2half2_rn(v.x * s, v.y * s);
    __half2 h1 = __floats2half2_rn(v.z * s, v.w * s);
    ((uint2*)dst)[i] = make_uint2(*(uint32_t*)&h0, *(uint32_t*)&h1);
}
__global__ __launch_bounds__(256) void convert_kernel(
    const float* __restrict__ x,  const float* __restrict__ Wq,
    const float* __restrict__ bq, const float* __restrict__ Wk,
    const float* __restrict__ Wv, const float* __restrict__ Wo)
{
    long long i = (long long)blockIdx.x * 256 + threadIdx.x;
    if (i < NX4) { cvt4(g_xh, x, i, 1.f); return; }
    i -= NX4;
    if (i < NW4) { cvt4(g_wqh, Wq, i, 0.125f * LOG2E); return; }
    i -= NW4;
    if (i < NW4) { cvt4(g_wkh, Wk, i, 1.f); return; }
    i -= NW4;
    if (i < NW4) { cvt4(g_wvh, Wv, i, 1.f); return; }
    i -= NW4;
    if (i < ND4) { cvt4(g_woh, Wo, i, 1.f); return; }
    i -= ND4;
    if (i < H_ * HD_) g_bqs[i] = bq[i] * 0.125f * LOG2E;
}

// ---------------------------------------------------------------------------
// QKV projection (fp16): 512 threads, 128x256x32, warp tile 32x64.
// 3-buffer ring. sA [row][k] stride 40; sB [k][n] stride 264 (trans ldmatrix).
// grid (32, 4, 3).
// ---------------------------------------------------------------------------
#define QA_ST 40
#define QAW   (128 * QA_ST)
#define QB_ST 264
#define QBW   (32 * QB_ST)
#define QSTG  (QAW + QBW)
#define QKV_SMEM (3 * QSTG * 2)   // 81408 bytes

__global__ __launch_bounds__(512, 1) void qkv_kernel(
    const float* __restrict__ bk, const float* __restrict__ bv)
{
    extern __shared__ __half hsm[];
    const int rt = blockIdx.x, hp = blockIdx.y, m = blockIdx.z;
    const __half* W    = (m == 0) ? g_wqh : (m == 1) ? g_wkh : g_wvh;
    const float*  bias = (m == 0) ? g_bqs : (m == 1) ? bk : bv;
    __half*       out  = (m == 0) ? g_q : (m == 1) ? g_k : g_v;

    const int tid  = threadIdx.x;
    const int wid  = tid >> 5;
    const int lane = tid & 31;
    const int wm   = wid >> 2, wn = wid & 3;
    const int ql   = lane & 3, qr = lane >> 2;
    const int row0 = rt * 128;
    const int h0   = hp * 4;

    const uint32_t sm0 = smem_u32(hsm);
    const uint32_t aLane = ((wm * 32 + (lane & 15)) * QA_ST) * 2 + (lane >> 4) * 16;
    const int klane = (lane & 7) + ((lane >> 3) & 1) * 8;
    const uint32_t bLane = (klane * QB_ST + (lane >> 4) * 8 + wn * 64) * 2;

    float acc[2][8][4];
    #pragma unroll
    for (int mi = 0; mi < 2; mi++)
        #pragma unroll
        for (int ni = 0; ni < 8; ni++)
            #pragma unroll
            for (int c = 0; c < 4; c++) acc[mi][ni][c] = 0.f;

    #define QKV_STAGE(c, s) {                                                  \
        uint32_t sb = sm0 + (s) * QSTG * 2;                                    \
        {   int g = tid; int row = g >> 2; int kg = (g & 3) * 8;               \
            CP16(sb + (row * QA_ST + kg) * 2,                                  \
                 &g_xh[(size_t)(row0 + row) * D_ + (c) * 32 + kg]);            \
        }                                                                      \
        _Pragma("unroll")                                                      \
        for (int i = 0; i < 2; i++) {                                          \
            int g = i * 512 + tid; int k = g >> 5; int n8 = (g & 31) * 8;      \
            CP16(sb + (QAW + k * QB_ST + n8) * 2,                              \
                 &W[((size_t)(h0 + (n8 >> 6)) * D_ + (c) * 32 + k) * HD_ + (n8 & 63)]); \
        }                                                                      \
    }

    QKV_STAGE(0, 0); CPCOMMIT();
    QKV_STAGE(1, 1); CPCOMMIT();

    for (int c = 0; c < 32; c++) {
        const int cur = c % 3;
        CPWAIT(1);
        __syncthreads();
        if (c + 2 < 32) { QKV_STAGE(c + 2, (c + 2) % 3); }
        CPCOMMIT();

        const uint32_t sAb = sm0 + cur * QSTG * 2;
        const uint32_t sBb = sAb + QAW * 2;

        #pragma unroll
        for (int kk = 0; kk < 2; kk++) {
            uint32_t a[2][4];
            #pragma unroll
            for (int mi = 0; mi < 2; mi++)
                ldm4(a[mi], sAb + aLane + mi * 16 * QA_ST * 2 + kk * 32);
            uint32_t bb[4][4];
            #pragma unroll
            for (int nj = 0; nj < 4; nj++)
                ldm4t(bb[nj], sBb + bLane + (kk * 16 * QB_ST + nj * 16) * 2);
            #pragma unroll
            for (int mi = 0; mi < 2; mi++)
                #pragma unroll
                for (int nj = 0; nj < 4; nj++) {
                    mma_f16(acc[mi][2 * nj],     a[mi], bb[nj][0], bb[nj][1]);
                    mma_f16(acc[mi][2 * nj + 1], a[mi], bb[nj][2], bb[nj][3]);
                }
        }
    }

    #pragma unroll
    for (int mi = 0; mi < 2; mi++) {
        int row = row0 + wm * 32 + mi * 16 + qr;
        int bb2 = row >> 11;
        int s   = row & (S_ - 1);
        #pragma unroll
        for (int ni = 0; ni < 8; ni++) {
            int cl = wn * 64 + ni * 8 + 2 * ql;
            int h  = h0 + (cl >> 6);
            int e  = cl & 63;
            float bv0 = bias[h * HD_ + e];
            float bv1 = bias[h * HD_ + e + 1];
            __half* p0 = out + (((size_t)bb2 * H_ + h) * S_ + s) * HD_ + e;
            __half* p1 = out + (((size_t)bb2 * H_ + h) * S_ + s + 8) * HD_ + e;
            *(__half2*)p0 = __floats2half2_rn(acc[mi][ni][0] + bv0, acc[mi][ni][1] + bv1);
            *(__half2*)p1 = __floats2half2_rn(acc[mi][ni][2] + bv0, acc[mi][ni][3] + bv1);
        }
    }
}

// ---------------------------------------------------------------------------
// Flash attention (causal, fp16, exp2-domain, no running max).
// P packed to fp16 A-fragments IMMEDIATELY (16 uint32 live, sc dead by PV).
// 128 queries/block, 8 warps x 16 rows, double-buffered K/V.
// grid (16 reversed, 32), 256 threads, occupancy 2.
// ---------------------------------------------------------------------------
#define AT_ST 72
#define AK_W (64 * AT_ST)
#define AV_W (64 * AT_ST)
#define AQ_OFF (2 * AK_W + 2 * AV_W)
#define AQ_W  (128 * AT_ST)
#define ATT_SMEM ((AQ_OFF + AQ_W) * 2)

__global__ __launch_bounds__(256, 2) void attn_kernel()
{
    extern __shared__ __half hsm[];

    const int qt = 15 - blockIdx.x;
    const int bh = blockIdx.y;
    const int b  = bh >> 4;
    const int h  = bh & 15;
    const int tid  = threadIdx.x;
    const int w    = tid >> 5;
    const int lane = tid & 31;
    const int qr   = lane >> 2;
    const int ql   = lane & 3;

    const __half* Qb = g_q + (size_t)bh * S_ * HD_;
    const __half* Kb = g_k + (size_t)bh * S_ * HD_;
    const __half* Vb = g_v + (size_t)bh * S_ * HD_;

    const uint32_t sk_b = smem_u32(hsm);
    const uint32_t sv_b = sk_b + 2 * AK_W * 2;
    const uint32_t sq_b = sk_b + AQ_OFF * 2;
    const uint32_t aoff = ((w * 16 + (lane & 15)) * AT_ST) * 2 + (lane >> 4) * 16;
    const uint32_t koff = ((lane & 15) * AT_ST) * 2 + (lane >> 4) * 16;
    const int klane = (lane & 7) + ((lane >> 3) & 1) * 8;
    const uint32_t voff = (klane * AT_ST + (lane >> 4) * 8) * 2;

    // ---- stage Q (exp2-domain pre-scaled), extract A fragments ----
    #pragma unroll
    for (int i = 0; i < 4; i++) {
        int g = i * 256 + tid;
        int row = g >> 3, kg = (g & 7) * 8;
        CP16(sq_b + (row * AT_ST + kg) * 2, &Qb[(size_t)(qt * 128 + row) * HD_ + kg]);
    }
    CPCOMMIT(); CPWAIT(0);
    __syncthreads();

    uint32_t qa[4][4];
    #pragma unroll
    for (int kk = 0; kk < 4; kk++) ldm4(qa[kk], sq_b + aoff + kk * 32);

    #define ATT_STAGE(kt, s) {                                                 \
        _Pragma("unroll")                                                      \
        for (int i = 0; i < 4; i++) {                                          \
            int g = i * 256 + tid;                                             \
            int sel = g >> 9; int row = (g >> 3) & 63; int kg = (g & 7) * 8;   \
            uint32_t base = sel ? (sv_b + (s) * AV_W * 2) : (sk_b + (s) * AK_W * 2); \
            const __half* src = sel ? &Vb[(size_t)((kt) * 64 + row) * HD_ + kg] \
                                    : &Kb[(size_t)((kt) * 64 + row) * HD_ + kg]; \
            CP16(base + (row * AT_ST + kg) * 2, src);                          \
        }                                                                      \
    }

    ATT_STAGE(0, 0); CPCOMMIT();

    float O[8][4];
    #pragma unroll
    for (int n = 0; n < 8; n++)
        #pragma unroll
        for (int c = 0; c < 4; c++) O[n][c] = 0.f;
    float l0 = 0.f, l1 = 0.f;

    const int rbase = qt * 128 + w * 16;
    const int nkt = 2 * qt + 2;

    for (int kt = 0; kt < nkt; kt++) {
        const int buf = kt & 1;
        CPWAIT(0);
        __syncthreads();
        if (kt + 1 < nkt) { ATT_STAGE(kt + 1, buf ^ 1); }
        CPCOMMIT();

        if (kt * 64 > rbase + 15) continue;   // fully masked for this warp

        // ---- QK^T (exp2-domain logits) ----
        const uint32_t kbase = sk_b + buf * AK_W * 2;
        float sc[8][4];
        #pragma unroll
        for (int n = 0; n < 8; n++)
            #pragma unroll
            for (int c = 0; c < 4; c++) sc[n][c] = 0.f;
        #pragma unroll
        for (int kk = 0; kk < 4; kk++) {
            #pragma unroll
            for (int j = 0; j < 4; j++) {
                uint32_t kb[4];
                ldm4(kb, kbase + koff + j * 16 * AT_ST * 2 + kk * 32);
                mma_f16(sc[2 * j],     qa[kk], kb[0], kb[2]);
                mma_f16(sc[2 * j + 1], qa[kk], kb[1], kb[3]);
            }
        }

        if (kt * 64 + 63 > rbase) {    // partial causal mask
            const int r0 = rbase + qr;
            const int c0 = kt * 64;
            #pragma unroll
            for (int n = 0; n < 8; n++) {
                int cg = c0 + n * 8 + 2 * ql;
                if (cg     > r0)     sc[n][0] = -1e30f;
                if (cg + 1 > r0)     sc[n][1] = -1e30f;
                if (cg     > r0 + 8) sc[n][2] = -1e30f;
                if (cg + 1 > r0 + 8) sc[n][3] = -1e30f;
            }
        }

        // ---- p = exp2(s), accumulate sums, pack to fp16 A-frags NOW ----
        uint32_t pa[4][4];
        #pragma unroll
        for (int kk = 0; kk < 4; kk++) {
            float e00 = exp2f(sc[2 * kk][0]),     e01 = exp2f(sc[2 * kk][1]);
            float e02 = exp2f(sc[2 * kk][2]),     e03 = exp2f(sc[2 * kk][3]);
            float e10 = exp2f(sc[2 * kk + 1][0]), e11 = exp2f(sc[2 * kk + 1][1]);
            float e12 = exp2f(sc[2 * kk + 1][2]), e13 = exp2f(sc[2 * kk + 1][3]);
            l0 += e00 + e01 + e10 + e11;
            l1 += e02 + e03 + e12 + e13;
            pa[kk][0] = PK2(e00, e01);
            pa[kk][1] = PK2(e02, e03);
            pa[kk][2] = PK2(e10, e11);
            pa[kk][3] = PK2(e12, e13);
        }

        // ---- P @ V, P directly as A-fragments ----
        const uint32_t vbase = sv_b + buf * AV_W * 2;
        #pragma unroll
        for (int kk = 0; kk < 4; kk++) {
            #pragma unroll
            for (int j = 0; j < 4; j++) {
                uint32_t vb[4];
                ldm4t(vb, vbase + voff + (kk * 16 * AT_ST + j * 16) * 2);
                mma_f16(O[2 * j],     pa[kk], vb[0], vb[1]);
                mma_f16(O[2 * j + 1], pa[kk], vb[2], vb[3]);
            }
        }
    }

    // ---- reduce l across the quad, normalize, store ----
    l0 += __shfl_xor_sync(0xffffffffu, l0, 1);
    l0 += __shfl_xor_sync(0xffffffffu, l0, 2);
    l1 += __shfl_xor_sync(0xffffffffu, l1, 1);
    l1 += __shfl_xor_sync(0xffffffffu, l1, 2);
    float inv0 = 1.f / l0, inv1 = 1.f / l1;
    int r0g = qt * 128 + w * 16 + qr;
    __half* base0 = g_wv + ((size_t)b * S_ + r0g) * D_ + h * HD_;
    __half* base1 = g_wv + ((size_t)b * S_ + r0g + 8) * D_ + h * HD_;
    #pragma unroll
    for (int n = 0; n < 8; n++) {
        int cc = n * 8 + 2 * ql;
        *(__half2*)&base0[cc] = __floats2half2_rn(O[n][0] * inv0, O[n][1] * inv0);
        *(__half2*)&base1[cc] = __floats2half2_rn(O[n][2] * inv1, O[n][3] * inv1);
    }
}

// ---------------------------------------------------------------------------
// Output projection (fp16): 512 threads, 128x256x32, 3-buffer ring.
// A [row][k], B [n][k] stride 40, non-trans ldmatrix. grid (32, 4).
// ---------------------------------------------------------------------------
#define OA_ST 40
#define OAW   (128 * OA_ST)
#define OBW   (256 * OA_ST)
#define OSTG  (OAW + OBW)
#define OP_SMEM (3 * OSTG * 2)   // 92160 bytes

__global__ __launch_bounds__(512, 1) void oproj_kernel(
    const float* __restrict__ bo, float* __restrict__ out)
{
    extern __shared__ __half hsm[];
    const int rt = blockIdx.x, ct = blockIdx.y;

    const int tid  = threadIdx.x;
    const int wid  = tid >> 5;
    const int lane = tid & 31;
    const int wm   = wid >> 2, wn = wid & 3;
    const int ql   = lane & 3, qr = lane >> 2;
    const int row0 = rt * 128;
    const int col0 = ct * 256;

    const uint32_t sm0 = smem_u32(hsm);
    const uint32_t aLane = ((wm * 32 + (lane & 15)) * OA_ST) * 2 + (lane >> 4) * 16;
    const uint32_t bLane = ((wn * 64 + (lane & 15)) * OA_ST) * 2 + (lane >> 4) * 16;

    float acc[2][8][4];
    #pragma unroll
    for (int mi = 0; mi < 2; mi++)
        #pragma unroll
        for (int ni = 0; ni < 8; ni++)
            #pragma unroll
            for (int c = 0; c < 4; c++) acc[mi][ni][c] = 0.f;

    #define OP_STAGE(c, s) {                                                   \
        uint32_t sb = sm0 + (s) * OSTG * 2;                                    \
        {   int g = tid; int row = g >> 2; int kg = (g & 3) * 8;               \
            CP16(sb + (row * OA_ST + kg) * 2,                                  \
                 &g_wv[(size_t)(row0 + row) * D_ + (c) * 32 + kg]);            \
        }                                                                      \
        _Pragma("unroll")                                                      \
        for (int i = 0; i < 2; i++) {                                          \
            int g = i * 512 + tid; int n = g >> 2; int kg = (g & 3) * 8;       \
            CP16(sb + (OAW + n * OA_ST + kg) * 2,                              \
                 &g_woh[(size_t)(col0 + n) * D_ + (c) * 32 + kg]);             \
        }                                                                      \
    }

    OP_STAGE(0, 0); CPCOMMIT();
    OP_STAGE(1, 1); CPCOMMIT();

    for (int c = 0; c < 32; c++) {
        const int cur = c % 3;
        CPWAIT(1);
        __syncthreads();
        if (c + 2 < 32) { OP_STAGE(c + 2, (c + 2) % 3); }
        CPCOMMIT();

        const uint32_t sAb = sm0 + cur * OSTG * 2;
        const uint32_t sBb = sAb + OAW * 2;

        #pragma unroll
        for (int kk = 0; kk < 2; kk++) {
            uint32_t a[2][4];
            #pragma unroll
            for (int mi = 0; mi < 2; mi++)
                ldm4(a[mi], sAb + aLane + mi * 16 * OA_ST * 2 + kk * 32);
            uint32_t bb[4][4];
            #pragma unroll
            for (int nj = 0; nj < 4; nj++)
                ldm4(bb[nj], sBb + bLane + nj * 16 * OA_ST * 2 + kk * 32);
            #pragma unroll
            for (int mi = 0; mi < 2; mi++)
                #pragma unroll
                for (int nj = 0; nj < 4; nj++) {
                    mma_f16(acc[mi][2 * nj],     a[mi], bb[nj][0], bb[nj][2]);
                    mma_f16(acc[mi][2 * nj + 1], a[mi], bb[nj][1], bb[nj][3]);
                }
        }
    }

    #pragma unroll
    for (int mi = 0; mi < 2; mi++) {
        int row = row0 + wm * 32 + mi * 16 + qr;
        #pragma unroll
        for (int ni = 0; ni < 8; ni++) {
            int col = col0 + wn * 64 + ni * 8 + 2 * ql;
            float bv0 = bo[col], bv1 = bo[col + 1];
            *(float2*)&out[(size_t)row * D_ + col] =
                make_float2(acc[mi][ni][0] + bv0, acc[mi][ni][1] + bv1);
            *(float2*)&out[(size_t)(row + 8) * D_ + col] =
                make_float2(acc[mi][ni][2] + bv0, acc[mi][ni][3] + bv1);
        }
    }
}

// ---------------------------------------------------------------------------
// Launch. metadata order: x, Wq, bq, Wk, bk, Wv, bv, Wo, bo
// ---------------------------------------------------------------------------
extern "C" void kernel_launch(void* const* d_in, const int* in_sizes, int n_in,
                              void* d_out, int out_size)
{
    const float* x  = (const float*)d_in[0];
    const float* Wq = (const float*)d_in[1];
    const float* bq = (const float*)d_in[2];
    const float* Wk = (const float*)d_in[3];
    const float* bk = (const float*)d_in[4];
    const float* Wv = (const float*)d_in[5];
    const float* bv = (const float*)d_in[6];
    const float* Wo = (const float*)d_in[7];
    const float* bo = (const float*)d_in[8];
    float* out = (float*)d_out;

    cudaFuncSetAttribute(qkv_kernel,   cudaFuncAttributeMaxDynamicSharedMemorySize, QKV_SMEM);
    cudaFuncSetAttribute(attn_kernel,  cudaFuncAttributeMaxDynamicSharedMemorySize, ATT_SMEM);
    cudaFuncSetAttribute(oproj_kernel, cudaFuncAttributeMaxDynamicSharedMemorySize, OP_SMEM);

    const long long ntot = (long long)NX4 + 3LL * NW4 + ND4 + H_ * HD_;
    convert_kernel<<<(int)((ntot + 255) / 256), 256>>>(x, Wq, bq, Wk, Wv, Wo);

    qkv_kernel<<<dim3(BS_ / 128, H_ / 4, 3), 512, QKV_SMEM>>>(bk, bv);

    attn_kernel<<<dim3(16, 32), 256, ATT_SMEM>>>();

    oproj_kernel<<<dim3(BS_ / 128, D_ / 256), 512, OP_SMEM>>>(bo, out);
}